// round 8
// baseline (speedup 1.0000x reference)
#include <cuda_runtime.h>
#include <cuda_fp16.h>

#define NN 20000
#define EE 320000
#define BCAP 128
#define LOG2E 1.44269504f

// ---------------- scratch ----------------
__device__ __half g_h[NN * 256];
__device__ __half g_x2[NN * 256];
__device__ float  g_h1[NN * 64];
__device__ float  g_as1[NN * 4];     // pre-scaled by LOG2E
__device__ float  g_ad1[NN * 4];
__device__ float  g_as2[NN * 4];
__device__ float  g_ad2[NN * 4];
__device__ float  g_xfsq[NN];
__device__ __half g_nsf[NN * 32];
__device__ float2 g_ninfo[NN];       // {sqrt(trust), xfinv}
__device__ int    g_cnt[NN];
__device__ int    g_srcs[NN * BCAP];
__device__ float  g_bnsum[64];
__device__ float  g_bnsq[64];
__device__ float  g_mu[64];
__device__ float  g_istd[64];

__device__ __forceinline__ float lrelu(float x) { return x > 0.f ? x : 0.2f * x; }

__device__ __forceinline__ float ex2(float x) {
    float r; asm("ex2.approx.f32 %0, %1;" : "=f"(r) : "f"(x)); return r;
}
__device__ __forceinline__ float frcp(float x) {
    float r; asm("rcp.approx.f32 %0, %1;" : "=f"(r) : "f"(x)); return r;
}

__device__ __forceinline__ void cvt8(uint4 u, float4& f0, float4& f1) {
    float2 a = __half22float2(*(__half2*)&u.x);
    float2 b = __half22float2(*(__half2*)&u.y);
    float2 c = __half22float2(*(__half2*)&u.z);
    float2 d = __half22float2(*(__half2*)&u.w);
    f0 = make_float4(a.x, a.y, b.x, b.y);
    f1 = make_float4(c.x, c.y, d.x, d.y);
}

// ---------------- init ----------------
__global__ void k_init() {
    int i = blockIdx.x * blockDim.x + threadIdx.x;
    if (i < NN) { g_cnt[i] = 0; g_xfsq[i] = 0.f; }
    if (i < 64) { g_bnsum[i] = 0.f; g_bnsq[i] = 0.f; }
}

// ---------------- bucketed CSR: 4 edges / thread ----------------
__global__ void k_scatter(const int* __restrict__ ei) {
    int e0 = (blockIdx.x * blockDim.x + threadIdx.x) * 4;
    if (e0 + 3 < EE) {
        int4 s4 = *(const int4*)&ei[e0];
        int4 d4 = *(const int4*)&ei[EE + e0];
        int p0 = atomicAdd(&g_cnt[d4.x], 1);
        int p1 = atomicAdd(&g_cnt[d4.y], 1);
        int p2 = atomicAdd(&g_cnt[d4.z], 1);
        int p3 = atomicAdd(&g_cnt[d4.w], 1);
        if (p0 < BCAP) g_srcs[d4.x * BCAP + p0] = s4.x;
        if (p1 < BCAP) g_srcs[d4.y * BCAP + p1] = s4.y;
        if (p2 < BCAP) g_srcs[d4.z * BCAP + p2] = s4.z;
        if (p3 < BCAP) g_srcs[d4.w * BCAP + p3] = s4.w;
    } else {
        for (int e = e0; e < EE; e++) {
            int i = ei[EE + e];
            int p = atomicAdd(&g_cnt[i], 1);
            if (p < BCAP) g_srcs[i * BCAP + p] = ei[e];
        }
    }
}

// ------- tensor-core GEMM + fused attention-score / row-ssq epilogue ---------
#define MMA16816(c, a0, a1, a2, a3, b0, b1)                                   \
    asm volatile(                                                             \
        "mma.sync.aligned.m16n8k16.row.col.f32.f16.f16.f32 "                  \
        "{%0,%1,%2,%3},{%4,%5,%6,%7},{%8,%9},{%0,%1,%2,%3};"                  \
        : "+f"(c[0]), "+f"(c[1]), "+f"(c[2]), "+f"(c[3])                      \
        : "r"(a0), "r"(a1), "r"(a2), "r"(a3), "r"(b0), "r"(b1))

#define LDSM4(r0, r1, r2, r3, addr)                                           \
    asm volatile("ldmatrix.sync.aligned.m8n8.x4.shared.b16 {%0,%1,%2,%3},[%4];" \
                 : "=r"(r0), "=r"(r1), "=r"(r2), "=r"(r3) : "r"(addr))

__global__ void __launch_bounds__(256) k_gemm_mma(
    const float* __restrict__ A, const float* __restrict__ B,
    __half* __restrict__ C, int M, int K,
    const float* __restrict__ mu, const float* __restrict__ istd,
    const float* __restrict__ asrc, const float* __restrict__ adst,
    float* __restrict__ as_o, float* __restrict__ ad_o,
    float* __restrict__ ssq) {
    __shared__ __half As[64][136];
    __shared__ __half Bs[64][136];
    __shared__ float s_sa[64], s_da[64], s_ps[64], s_pd[64], s_q[64];
    int tid = threadIdx.x;
    int m0 = blockIdx.x * 64, n0 = blockIdx.y * 64;
    int K4 = K >> 2;

    if (tid < 64) {
        s_sa[tid] = asrc[n0 + tid];
        s_da[tid] = adst[n0 + tid];
        s_ps[tid] = 0.f; s_pd[tid] = 0.f; s_q[tid] = 0.f;
    }
    for (int v = tid; v < 64 * K4; v += 256) {
        int r = v / K4, c = (v % K4) * 4;
        float4 a = make_float4(0.f, 0.f, 0.f, 0.f);
        if (m0 + r < M) a = *(const float4*)&A[(size_t)(m0 + r) * K + c];
        if (mu) {
            float4 m4 = *(const float4*)&mu[c];
            float4 s4 = *(const float4*)&istd[c];
            a.x = (a.x - m4.x) * s4.x;
            a.y = (a.y - m4.y) * s4.y;
            a.z = (a.z - m4.z) * s4.z;
            a.w = (a.w - m4.w) * s4.w;
        }
        *(__half2*)&As[r][c]     = __floats2half2_rn(a.x, a.y);
        *(__half2*)&As[r][c + 2] = __floats2half2_rn(a.z, a.w);
    }
    for (int v = tid; v < 64 * K4; v += 256) {
        int r = v / K4, c = (v % K4) * 4;
        float4 b = *(const float4*)&B[(size_t)(n0 + r) * K + c];
        *(__half2*)&Bs[r][c]     = __floats2half2_rn(b.x, b.y);
        *(__half2*)&Bs[r][c + 2] = __floats2half2_rn(b.z, b.w);
    }
    __syncthreads();

    int w = tid >> 5, lane = tid & 31;
    int mw = (w & 3) * 16, nw = (w >> 2) * 32;
    float c0[4] = {0.f, 0.f, 0.f, 0.f};
    float c1[4] = {0.f, 0.f, 0.f, 0.f};
    float c2[4] = {0.f, 0.f, 0.f, 0.f};
    float c3[4] = {0.f, 0.f, 0.f, 0.f};

    unsigned aAddr = (unsigned)__cvta_generic_to_shared(
        &As[mw + (lane & 15)][(lane & 16) ? 8 : 0]);
    int brow = nw + (lane & 7) + ((lane & 16) ? 8 : 0);
    unsigned bAddr0 = (unsigned)__cvta_generic_to_shared(
        &Bs[brow][(lane & 8) ? 8 : 0]);
    unsigned bAddr1 = bAddr0 + 16 * 136 * 2;

    for (int k0 = 0; k0 < K; k0 += 16) {
        unsigned a0, a1, a2, a3, p0, p1, p2, p3, q0, q1, q2, q3;
        LDSM4(a0, a1, a2, a3, aAddr + k0 * 2);
        LDSM4(p0, p1, p2, p3, bAddr0 + k0 * 2);
        LDSM4(q0, q1, q2, q3, bAddr1 + k0 * 2);
        MMA16816(c0, a0, a1, a2, a3, p0, p1);
        MMA16816(c1, a0, a1, a2, a3, p2, p3);
        MMA16816(c2, a0, a1, a2, a3, q0, q1);
        MMA16816(c3, a0, a1, a2, a3, q2, q3);
    }

    int r0 = m0 + mw + (lane >> 2);
    int colb = n0 + nw + 2 * (lane & 3);
    float* accs[4] = {c0, c1, c2, c3};
#pragma unroll
    for (int t = 0; t < 4; t++) {
        float* cc = accs[t];
        if (r0 < M)
            *(__half2*)&C[(size_t)r0 * 256 + colb + t * 8] =
                __floats2half2_rn(cc[0], cc[1]);
        if (r0 + 8 < M)
            *(__half2*)&C[(size_t)(r0 + 8) * 256 + colb + t * 8] =
                __floats2half2_rn(cc[2], cc[3]);
    }

    float ps = 0.f, pd = 0.f, q = 0.f, ps8 = 0.f, pd8 = 0.f, q8 = 0.f;
#pragma unroll
    for (int t = 0; t < 4; t++) {
        int col = nw + 2 * (lane & 3) + t * 8;
        float a0 = s_sa[col], a1 = s_sa[col + 1];
        float d0 = s_da[col], d1 = s_da[col + 1];
        float* cc = accs[t];
        ps  += cc[0] * a0 + cc[1] * a1;
        pd  += cc[0] * d0 + cc[1] * d1;
        q   += cc[0] * cc[0] + cc[1] * cc[1];
        ps8 += cc[2] * a0 + cc[3] * a1;
        pd8 += cc[2] * d0 + cc[3] * d1;
        q8  += cc[2] * cc[2] + cc[3] * cc[3];
    }
#pragma unroll
    for (int o = 1; o < 4; o <<= 1) {
        ps  += __shfl_xor_sync(0xffffffffu, ps, o);
        pd  += __shfl_xor_sync(0xffffffffu, pd, o);
        q   += __shfl_xor_sync(0xffffffffu, q, o);
        ps8 += __shfl_xor_sync(0xffffffffu, ps8, o);
        pd8 += __shfl_xor_sync(0xffffffffu, pd8, o);
        q8  += __shfl_xor_sync(0xffffffffu, q8, o);
    }
    if ((lane & 3) == 0) {
        int r = mw + (lane >> 2);
        atomicAdd(&s_ps[r], ps);  atomicAdd(&s_pd[r], pd);  atomicAdd(&s_q[r], q);
        atomicAdd(&s_ps[r + 8], ps8); atomicAdd(&s_pd[r + 8], pd8); atomicAdd(&s_q[r + 8], q8);
    }
    __syncthreads();
    if (tid < 64 && m0 + tid < M) {
        int head = blockIdx.y;
        as_o[(m0 + tid) * 4 + head] = s_ps[tid] * LOG2E;
        ad_o[(m0 + tid) * 4 + head] = s_pd[tid] * LOG2E;
        if (ssq) atomicAdd(&ssq[m0 + tid], s_q[tid]);
    }
}

// ---- node trust + normalized struct feat + feature-norm finalize ------------
__global__ void k_trust(const float* __restrict__ sf, const float* __restrict__ Wt,
                        const float* __restrict__ bt) {
    int gt = blockIdx.x * blockDim.x + threadIdx.x;
    int w = gt >> 5;
    int lane = threadIdx.x & 31;
    if (w >= NN) return;
    float v = sf[w * 32 + lane];
    float d = v * Wt[lane];
    float q = v * v;
#pragma unroll
    for (int o = 1; o < 32; o <<= 1) {
        d += __shfl_xor_sync(0xffffffffu, d, o);
        q += __shfl_xor_sync(0xffffffffu, q, o);
    }
    float sii = 1.0f / fmaxf(sqrtf(q), 1e-8f);
    g_nsf[w * 32 + lane] = __float2half(v * sii);
    if (lane == 0) {
        float2 ni;
        float trust = 1.0f / (1.0f + __expf(-(d + bt[0])));
        ni.x = sqrtf(trust);
        ni.y = 1.0f / fmaxf(sqrtf(g_xfsq[w]), 1e-8f);
        g_ninfo[w] = ni;
    }
}

// -------- layer-1: GAT aggregation + fused BN stats, warp per dst node -------
__global__ void k_l1(const float* __restrict__ bias1) {
    __shared__ float s_sum[64], s_sq[64];
    int tid = threadIdx.x;
    if (tid < 64) { s_sum[tid] = 0.f; s_sq[tid] = 0.f; }
    __syncthreads();

    int gt = blockIdx.x * blockDim.x + tid;
    int w = gt >> 5;
    int lane = tid & 31;
    if (w < NN) {
        int head = lane >> 3;
        float adv = g_ad1[w * 4 + head];
        float p0 = ex2(lrelu(g_as1[w * 4 + head] + adv));
        float s = p0;
        float4 f0, f1;
        cvt8(*(const uint4*)&g_h[w * 256 + lane * 8], f0, f1);
        float4 acc0, acc1;
        acc0.x = p0 * f0.x; acc0.y = p0 * f0.y; acc0.z = p0 * f0.z; acc0.w = p0 * f0.w;
        acc1.x = p0 * f1.x; acc1.y = p0 * f1.y; acc1.z = p0 * f1.z; acc1.w = p0 * f1.w;

        int end = min(g_cnt[w], BCAP);
        const int* __restrict__ bp = &g_srcs[w * BCAP];
#pragma unroll 2
        for (int e = 0; e < end; e++) {
            int j = __ldg(&bp[e]);
            float p = ex2(lrelu(__ldg(&g_as1[j * 4 + head]) + adv));
            float4 b0, b1;
            cvt8(*(const uint4*)&g_h[(size_t)j * 256 + lane * 8], b0, b1);
            s += p;
            acc0.x = fmaf(p, b0.x, acc0.x);
            acc0.y = fmaf(p, b0.y, acc0.y);
            acc0.z = fmaf(p, b0.z, acc0.z);
            acc0.w = fmaf(p, b0.w, acc0.w);
            acc1.x = fmaf(p, b1.x, acc1.x);
            acc1.y = fmaf(p, b1.y, acc1.y);
            acc1.z = fmaf(p, b1.z, acc1.z);
            acc1.w = fmaf(p, b1.w, acc1.w);
        }
        float r = frcp(s + 1e-16f);
        acc0.x *= r; acc0.y *= r; acc0.z *= r; acc0.w *= r;
        acc1.x *= r; acc1.y *= r; acc1.z *= r; acc1.w *= r;
#define HRED(v)                                     \
        v += __shfl_xor_sync(0xffffffffu, v, 8);    \
        v += __shfl_xor_sync(0xffffffffu, v, 16);
        HRED(acc0.x) HRED(acc0.y) HRED(acc0.z) HRED(acc0.w)
        HRED(acc1.x) HRED(acc1.y) HRED(acc1.z) HRED(acc1.w)
#undef HRED
        // lanes 0-15 hold identical reduced values (0-7 == 8-15 replicas)
        if (lane < 16) {
            int l8 = lane & 7;
            const float4* bpb = (const float4*)&bias1[l8 * 8];
            float4 b0 = bpb[0], b1 = bpb[1];
            float4 o0, o1;
            o0.x = fmaxf(0.25f * acc0.x + b0.x, 0.f);
            o0.y = fmaxf(0.25f * acc0.y + b0.y, 0.f);
            o0.z = fmaxf(0.25f * acc0.z + b0.z, 0.f);
            o0.w = fmaxf(0.25f * acc0.w + b0.w, 0.f);
            o1.x = fmaxf(0.25f * acc1.x + b1.x, 0.f);
            o1.y = fmaxf(0.25f * acc1.y + b1.y, 0.f);
            o1.z = fmaxf(0.25f * acc1.z + b1.z, 0.f);
            o1.w = fmaxf(0.25f * acc1.w + b1.w, 0.f);
            int c = l8 * 8;
            if (lane < 8) {
                float4* op = (float4*)&g_h1[w * 64 + c];
                op[0] = o0;
                op[1] = o1;
                atomicAdd(&s_sum[c + 0], o0.x);
                atomicAdd(&s_sum[c + 1], o0.y);
                atomicAdd(&s_sum[c + 2], o0.z);
                atomicAdd(&s_sum[c + 3], o0.w);
                atomicAdd(&s_sum[c + 4], o1.x);
                atomicAdd(&s_sum[c + 5], o1.y);
                atomicAdd(&s_sum[c + 6], o1.z);
                atomicAdd(&s_sum[c + 7], o1.w);
            } else {
                atomicAdd(&s_sq[c + 0], o0.x * o0.x);
                atomicAdd(&s_sq[c + 1], o0.y * o0.y);
                atomicAdd(&s_sq[c + 2], o0.z * o0.z);
                atomicAdd(&s_sq[c + 3], o0.w * o0.w);
                atomicAdd(&s_sq[c + 4], o1.x * o1.x);
                atomicAdd(&s_sq[c + 5], o1.y * o1.y);
                atomicAdd(&s_sq[c + 6], o1.z * o1.z);
                atomicAdd(&s_sq[c + 7], o1.w * o1.w);
            }
        }
    }
    __syncthreads();
    if (tid < 64) {
        atomicAdd(&g_bnsum[tid], s_sum[tid]);
        atomicAdd(&g_bnsq[tid], s_sq[tid]);
    }
}

__global__ void k_bnfin() {
    int c = threadIdx.x;
    if (c < 64) {
        float mu = g_bnsum[c] / (float)NN;
        float var = g_bnsq[c] / (float)NN - mu * mu;
        g_mu[c] = mu;
        g_istd[c] = rsqrtf(fmaxf(var, 0.f) + 1e-5f);
    }
}

// -------- layer-2: hybrid-gated GAT, 2-edge interleaved, warp per node -------
__global__ void k_l2(const float* __restrict__ We1, const float* __restrict__ be1,
                     const float* __restrict__ We2, const float* __restrict__ be2,
                     const float* __restrict__ betas, const float* __restrict__ bias2,
                     float* __restrict__ out) {
    __shared__ float sw[64];
    int tid = threadIdx.x;
    if (tid < 32) sw[tid] = We1[tid];
    else if (tid < 40) sw[tid] = be1[tid - 32];
    else if (tid < 48) sw[tid] = We2[tid - 40] * LOG2E;
    else if (tid == 48) sw[48] = be2[0] * LOG2E;
    else if (tid < 54) sw[tid] = betas[tid - 49] * LOG2E;
    __syncthreads();

    int gt = blockIdx.x * blockDim.x + tid;
    int w = gt >> 5;
    int lane = tid & 31;
    if (w >= NN) return;
    int head = lane >> 3;
    int hu_row = lane & 7;
    float w0 = sw[hu_row * 4 + 0], w1 = sw[hu_row * 4 + 1];
    float w2 = sw[hu_row * 4 + 2], w3 = sw[hu_row * 4 + 3];
    float wb = sw[32 + hu_row], wo = sw[40 + hu_row];
    float g48 = sw[48], g49 = sw[49], g50 = sw[50], g51 = sw[51], g52 = sw[52], g53 = sw[53];

    float4 xi0, xi1;
    cvt8(*(const uint4*)&g_x2[w * 256 + lane * 8], xi0, xi1);
    float nsfi = __half2float(g_nsf[w * 32 + lane]);
    float adv = g_ad2[w * 4 + head];
    float2 nw = g_ninfo[w];
    float tisq = nw.x, xii = nw.y;

    float s = 0.f;
    float4 acc0 = make_float4(0.f, 0.f, 0.f, 0.f);
    float4 acc1 = make_float4(0.f, 0.f, 0.f, 0.f);

    int end = min(g_cnt[w], BCAP);
    const int* __restrict__ bp = &g_srcs[w * BCAP];
    int e = 0;
    for (; e + 1 < end; e += 2) {
        int ja = __ldg(&bp[e]);
        int jb = __ldg(&bp[e + 1]);
        uint4 ua = *(const uint4*)&g_x2[(size_t)ja * 256 + lane * 8];
        uint4 ub = *(const uint4*)&g_x2[(size_t)jb * 256 + lane * 8];
        float nsfa = __half2float(__ldg(&g_nsf[ja * 32 + lane]));
        float nsfb = __half2float(__ldg(&g_nsf[jb * 32 + lane]));
        float2 na = __ldg(&g_ninfo[ja]);
        float2 nb = __ldg(&g_ninfo[jb]);
        float aja = __ldg(&g_as2[ja * 4 + head]);
        float ajb = __ldg(&g_as2[jb * 4 + head]);
        float4 a0, a1, b0, b1;
        cvt8(ua, a0, a1);
        cvt8(ub, b0, b1);
        float fda = a0.x * xi0.x + a0.y * xi0.y + a0.z * xi0.z + a0.w * xi0.w +
                    a1.x * xi1.x + a1.y * xi1.y + a1.z * xi1.z + a1.w * xi1.w;
        float fdb = b0.x * xi0.x + b0.y * xi0.y + b0.z * xi0.z + b0.w * xi0.w +
                    b1.x * xi1.x + b1.y * xi1.y + b1.z * xi1.z + b1.w * xi1.w;
        float sda = nsfa * nsfi;
        float sdb = nsfb * nsfi;
#pragma unroll
        for (int o = 1; o < 32; o <<= 1) {
            fda += __shfl_xor_sync(0xffffffffu, fda, o);
            fdb += __shfl_xor_sync(0xffffffffu, fdb, o);
            sda += __shfl_xor_sync(0xffffffffu, sda, o);
            sdb += __shfl_xor_sync(0xffffffffu, sdb, o);
        }
        float fsa = fda * xii * na.y;
        float fsb = fdb * xii * nb.y;
        float aga = sda * fsa, agb = sdb * fsb;
        float cfa = fabsf(sda - fsa), cfb = fabsf(sdb - fsb);
        float hua = w0 * sda + w1 * fsa + w2 * aga + w3 * cfa + wb;
        float hub = w0 * sdb + w1 * fsb + w2 * agb + w3 * cfb + wb;
        hua = fmaxf(hua, 0.f) * wo;
        hub = fmaxf(hub, 0.f) * wo;
#pragma unroll
        for (int o = 1; o < 8; o <<= 1) {
            hua += __shfl_xor_sync(0xffffffffu, hua, o);
            hub += __shfl_xor_sync(0xffffffffu, hub, o);
        }
        float eba = frcp(1.0f + ex2(-(hua + g48))) * fmaxf(aga, 0.f);
        float ebb = frcp(1.0f + ex2(-(hub + g48))) * fmaxf(agb, 0.f);
        float tba = na.x * tisq * fmaxf(0.5f * (sda + fsa), 0.f);
        float tbb = nb.x * tisq * fmaxf(0.5f * (sdb + fsb), 0.f);
        float gla = g49 * sda + g50 * fsa + g51 * aga + g52 * eba + g53 * tba;
        float glb = g49 * sdb + g50 * fsb + g51 * agb + g52 * ebb + g53 * tbb;
        float pa = ex2(lrelu(aja + adv) + gla);
        float pb = ex2(lrelu(ajb + adv) + glb);
        s += pa + pb;
        acc0.x = fmaf(pa, a0.x, fmaf(pb, b0.x, acc0.x));
        acc0.y = fmaf(pa, a0.y, fmaf(pb, b0.y, acc0.y));
        acc0.z = fmaf(pa, a0.z, fmaf(pb, b0.z, acc0.z));
        acc0.w = fmaf(pa, a0.w, fmaf(pb, b0.w, acc0.w));
        acc1.x = fmaf(pa, a1.x, fmaf(pb, b1.x, acc1.x));
        acc1.y = fmaf(pa, a1.y, fmaf(pb, b1.y, acc1.y));
        acc1.z = fmaf(pa, a1.z, fmaf(pb, b1.z, acc1.z));
        acc1.w = fmaf(pa, a1.w, fmaf(pb, b1.w, acc1.w));
    }
    if (e < end) {
        int j = __ldg(&bp[e]);
        uint4 u = *(const uint4*)&g_x2[(size_t)j * 256 + lane * 8];
        float nsfj = __half2float(__ldg(&g_nsf[j * 32 + lane]));
        float2 nj = __ldg(&g_ninfo[j]);
        float aj = __ldg(&g_as2[j * 4 + head]);
        float4 b0, b1;
        cvt8(u, b0, b1);
        float fd = b0.x * xi0.x + b0.y * xi0.y + b0.z * xi0.z + b0.w * xi0.w +
                   b1.x * xi1.x + b1.y * xi1.y + b1.z * xi1.z + b1.w * xi1.w;
        float sd = nsfj * nsfi;
#pragma unroll
        for (int o = 1; o < 32; o <<= 1) {
            fd += __shfl_xor_sync(0xffffffffu, fd, o);
            sd += __shfl_xor_sync(0xffffffffu, sd, o);
        }
        float fsim = fd * xii * nj.y;
        float ag = sd * fsim;
        float cf = fabsf(sd - fsim);
        float hu = w0 * sd + w1 * fsim + w2 * ag + w3 * cf + wb;
        hu = fmaxf(hu, 0.f) * wo;
#pragma unroll
        for (int o = 1; o < 8; o <<= 1)
            hu += __shfl_xor_sync(0xffffffffu, hu, o);
        float eb = frcp(1.0f + ex2(-(hu + g48))) * fmaxf(ag, 0.f);
        float tb = nj.x * tisq * fmaxf(0.5f * (sd + fsim), 0.f);
        float gl = g49 * sd + g50 * fsim + g51 * ag + g52 * eb + g53 * tb;
        float p = ex2(lrelu(aj + adv) + gl);
        s += p;
        acc0.x = fmaf(p, b0.x, acc0.x);
        acc0.y = fmaf(p, b0.y, acc0.y);
        acc0.z = fmaf(p, b0.z, acc0.z);
        acc0.w = fmaf(p, b0.w, acc0.w);
        acc1.x = fmaf(p, b1.x, acc1.x);
        acc1.y = fmaf(p, b1.y, acc1.y);
        acc1.z = fmaf(p, b1.z, acc1.z);
        acc1.w = fmaf(p, b1.w, acc1.w);
    }
    float r = frcp(s + 1e-16f);
    acc0.x *= r; acc0.y *= r; acc0.z *= r; acc0.w *= r;
    acc1.x *= r; acc1.y *= r; acc1.z *= r; acc1.w *= r;
#define HRED(v)                                     \
    v += __shfl_xor_sync(0xffffffffu, v, 8);        \
    v += __shfl_xor_sync(0xffffffffu, v, 16);
    HRED(acc0.x) HRED(acc0.y) HRED(acc0.z) HRED(acc0.w)
    HRED(acc1.x) HRED(acc1.y) HRED(acc1.z) HRED(acc1.w)
#undef HRED
    if (lane < 8) {
        const float4* bpb = (const float4*)&bias2[lane * 8];
        float4 b0 = bpb[0], b1 = bpb[1];
        float4 o0, o1;
        o0.x = 0.25f * acc0.x + b0.x;
        o0.y = 0.25f * acc0.y + b0.y;
        o0.z = 0.25f * acc0.z + b0.z;
        o0.w = 0.25f * acc0.w + b0.w;
        o1.x = 0.25f * acc1.x + b1.x;
        o1.y = 0.25f * acc1.y + b1.y;
        o1.z = 0.25f * acc1.z + b1.z;
        o1.w = 0.25f * acc1.w + b1.w;
        float4* op = (float4*)&out[w * 64 + lane * 8];
        op[0] = o0;
        op[1] = o1;
    }
}

// ---------------- host launch ----------------
extern "C" void kernel_launch(void* const* d_in, const int* in_sizes, int n_in,
                              void* d_out, int out_size) {
    const float* x    = (const float*)d_in[0];
    const int*   ei   = (const int*)d_in[1];
    const float* sf   = (const float*)d_in[2];
    const float* W1   = (const float*)d_in[3];
    const float* as1w = (const float*)d_in[4];
    const float* ad1w = (const float*)d_in[5];
    const float* b1   = (const float*)d_in[6];
    const float* W2   = (const float*)d_in[7];
    const float* as2w = (const float*)d_in[8];
    const float* ad2w = (const float*)d_in[9];
    const float* b2   = (const float*)d_in[10];
    const float* Wt   = (const float*)d_in[11];
    const float* bt   = (const float*)d_in[12];
    const float* We1  = (const float*)d_in[13];
    const float* be1  = (const float*)d_in[14];
    const float* We2  = (const float*)d_in[15];
    const float* be2  = (const float*)d_in[16];
    const float* betas = (const float*)d_in[17];
    float* out = (float*)d_out;

    __half *hP, *x2P;
    float *h1P, *muP, *istdP, *as1P, *ad1P, *as2P, *ad2P, *xfqP;
    cudaGetSymbolAddress((void**)&hP, g_h);
    cudaGetSymbolAddress((void**)&x2P, g_x2);
    cudaGetSymbolAddress((void**)&h1P, g_h1);
    cudaGetSymbolAddress((void**)&muP, g_mu);
    cudaGetSymbolAddress((void**)&istdP, g_istd);
    cudaGetSymbolAddress((void**)&as1P, g_as1);
    cudaGetSymbolAddress((void**)&ad1P, g_ad1);
    cudaGetSymbolAddress((void**)&as2P, g_as2);
    cudaGetSymbolAddress((void**)&ad2P, g_ad2);
    cudaGetSymbolAddress((void**)&xfqP, g_xfsq);

    const int TPB = 256;
    int nodeBlocks = (NN * 32 + TPB - 1) / TPB;

    k_init<<<(NN + TPB - 1) / TPB, TPB>>>();
    k_scatter<<<(EE / 4 + TPB - 1) / TPB, TPB>>>(ei);

    k_gemm_mma<<<dim3((NN + 63) / 64, 4), 256>>>(x, W1, hP, NN, 128,
                                                 nullptr, nullptr,
                                                 as1w, ad1w, as1P, ad1P, nullptr);
    k_l1<<<nodeBlocks, TPB>>>(b1);
    k_bnfin<<<1, 64>>>();

    k_gemm_mma<<<dim3((NN + 63) / 64, 4), 256>>>(h1P, W2, x2P, NN, 64,
                                                 muP, istdP,
                                                 as2w, ad2w, as2P, ad2P, xfqP);
    k_trust<<<nodeBlocks, TPB>>>(sf, Wt, bt);
    k_l2<<<nodeBlocks, TPB>>>(We1, be1, We2, be2, betas, b2, out);
}

// round 9
// speedup vs baseline: 1.0692x; 1.0692x over previous
#include <cuda_runtime.h>
#include <cuda_fp16.h>

#define NN 20000
#define EE 320000
#define BCAP 128
#define LOG2E 1.44269504f

// ---------------- scratch ----------------
__device__ __half g_h[NN * 256];
__device__ __half g_x2[NN * 256];
__device__ float  g_h1[NN * 64];
__device__ float  g_as1[NN * 4];     // pre-scaled by LOG2E
__device__ float  g_ad1[NN * 4];
__device__ float  g_as2[NN * 4];
__device__ float  g_ad2[NN * 4];
__device__ float  g_xfsq[NN];
__device__ __half g_nsf[NN * 32];
__device__ float2 g_ninfo[NN];       // {sqrt(trust), xfinv}
__device__ int    g_cnt[NN];
__device__ int    g_srcs[NN * BCAP];
__device__ float  g_bnsum[64];
__device__ float  g_bnsq[64];
__device__ float  g_mu[64];
__device__ float  g_istd[64];

__device__ __forceinline__ float lrelu(float x) { return x > 0.f ? x : 0.2f * x; }

__device__ __forceinline__ float ex2(float x) {
    float r; asm("ex2.approx.f32 %0, %1;" : "=f"(r) : "f"(x)); return r;
}
__device__ __forceinline__ float frcp(float x) {
    float r; asm("rcp.approx.f32 %0, %1;" : "=f"(r) : "f"(x)); return r;
}

__device__ __forceinline__ void cvt8(uint4 u, float4& f0, float4& f1) {
    float2 a = __half22float2(*(__half2*)&u.x);
    float2 b = __half22float2(*(__half2*)&u.y);
    float2 c = __half22float2(*(__half2*)&u.z);
    float2 d = __half22float2(*(__half2*)&u.w);
    f0 = make_float4(a.x, a.y, b.x, b.y);
    f1 = make_float4(c.x, c.y, d.x, d.y);
}

// ---------------- init ----------------
__global__ void k_init() {
    int i = blockIdx.x * blockDim.x + threadIdx.x;
    if (i < NN) { g_cnt[i] = 0; g_xfsq[i] = 0.f; }
    if (i < 64) { g_bnsum[i] = 0.f; g_bnsq[i] = 0.f; }
}

// ---------------- bucketed CSR: 4 edges / thread ----------------
__global__ void k_scatter(const int* __restrict__ ei) {
    int e0 = (blockIdx.x * blockDim.x + threadIdx.x) * 4;
    if (e0 + 3 < EE) {
        int4 s4 = *(const int4*)&ei[e0];
        int4 d4 = *(const int4*)&ei[EE + e0];
        int p0 = atomicAdd(&g_cnt[d4.x], 1);
        int p1 = atomicAdd(&g_cnt[d4.y], 1);
        int p2 = atomicAdd(&g_cnt[d4.z], 1);
        int p3 = atomicAdd(&g_cnt[d4.w], 1);
        if (p0 < BCAP) g_srcs[d4.x * BCAP + p0] = s4.x;
        if (p1 < BCAP) g_srcs[d4.y * BCAP + p1] = s4.y;
        if (p2 < BCAP) g_srcs[d4.z * BCAP + p2] = s4.z;
        if (p3 < BCAP) g_srcs[d4.w * BCAP + p3] = s4.w;
    } else {
        for (int e = e0; e < EE; e++) {
            int i = ei[EE + e];
            int p = atomicAdd(&g_cnt[i], 1);
            if (p < BCAP) g_srcs[i * BCAP + p] = ei[e];
        }
    }
}

// ------- tensor-core GEMM + fused attention-score / row-ssq epilogue ---------
#define MMA16816(c, a0, a1, a2, a3, b0, b1)                                   \
    asm volatile(                                                             \
        "mma.sync.aligned.m16n8k16.row.col.f32.f16.f16.f32 "                  \
        "{%0,%1,%2,%3},{%4,%5,%6,%7},{%8,%9},{%0,%1,%2,%3};"                  \
        : "+f"(c[0]), "+f"(c[1]), "+f"(c[2]), "+f"(c[3])                      \
        : "r"(a0), "r"(a1), "r"(a2), "r"(a3), "r"(b0), "r"(b1))

#define LDSM4(r0, r1, r2, r3, addr)                                           \
    asm volatile("ldmatrix.sync.aligned.m8n8.x4.shared.b16 {%0,%1,%2,%3},[%4];" \
                 : "=r"(r0), "=r"(r1), "=r"(r2), "=r"(r3) : "r"(addr))

__global__ void __launch_bounds__(256) k_gemm_mma(
    const float* __restrict__ A, const float* __restrict__ B,
    __half* __restrict__ C, int M, int K,
    const float* __restrict__ mu, const float* __restrict__ istd,
    const float* __restrict__ asrc, const float* __restrict__ adst,
    float* __restrict__ as_o, float* __restrict__ ad_o,
    float* __restrict__ ssq) {
    __shared__ __half As[64][136];
    __shared__ __half Bs[64][136];
    __shared__ float s_sa[64], s_da[64], s_ps[64], s_pd[64], s_q[64];
    int tid = threadIdx.x;
    int m0 = blockIdx.x * 64, n0 = blockIdx.y * 64;
    int K4 = K >> 2;

    if (tid < 64) {
        s_sa[tid] = asrc[n0 + tid];
        s_da[tid] = adst[n0 + tid];
        s_ps[tid] = 0.f; s_pd[tid] = 0.f; s_q[tid] = 0.f;
    }
    for (int v = tid; v < 64 * K4; v += 256) {
        int r = v / K4, c = (v % K4) * 4;
        float4 a = make_float4(0.f, 0.f, 0.f, 0.f);
        if (m0 + r < M) a = *(const float4*)&A[(size_t)(m0 + r) * K + c];
        if (mu) {
            float4 m4 = *(const float4*)&mu[c];
            float4 s4 = *(const float4*)&istd[c];
            a.x = (a.x - m4.x) * s4.x;
            a.y = (a.y - m4.y) * s4.y;
            a.z = (a.z - m4.z) * s4.z;
            a.w = (a.w - m4.w) * s4.w;
        }
        *(__half2*)&As[r][c]     = __floats2half2_rn(a.x, a.y);
        *(__half2*)&As[r][c + 2] = __floats2half2_rn(a.z, a.w);
    }
    for (int v = tid; v < 64 * K4; v += 256) {
        int r = v / K4, c = (v % K4) * 4;
        float4 b = *(const float4*)&B[(size_t)(n0 + r) * K + c];
        *(__half2*)&Bs[r][c]     = __floats2half2_rn(b.x, b.y);
        *(__half2*)&Bs[r][c + 2] = __floats2half2_rn(b.z, b.w);
    }
    __syncthreads();

    int w = tid >> 5, lane = tid & 31;
    int mw = (w & 3) * 16, nw = (w >> 2) * 32;
    float c0[4] = {0.f, 0.f, 0.f, 0.f};
    float c1[4] = {0.f, 0.f, 0.f, 0.f};
    float c2[4] = {0.f, 0.f, 0.f, 0.f};
    float c3[4] = {0.f, 0.f, 0.f, 0.f};

    unsigned aAddr = (unsigned)__cvta_generic_to_shared(
        &As[mw + (lane & 15)][(lane & 16) ? 8 : 0]);
    int brow = nw + (lane & 7) + ((lane & 16) ? 8 : 0);
    unsigned bAddr0 = (unsigned)__cvta_generic_to_shared(
        &Bs[brow][(lane & 8) ? 8 : 0]);
    unsigned bAddr1 = bAddr0 + 16 * 136 * 2;

    for (int k0 = 0; k0 < K; k0 += 16) {
        unsigned a0, a1, a2, a3, p0, p1, p2, p3, q0, q1, q2, q3;
        LDSM4(a0, a1, a2, a3, aAddr + k0 * 2);
        LDSM4(p0, p1, p2, p3, bAddr0 + k0 * 2);
        LDSM4(q0, q1, q2, q3, bAddr1 + k0 * 2);
        MMA16816(c0, a0, a1, a2, a3, p0, p1);
        MMA16816(c1, a0, a1, a2, a3, p2, p3);
        MMA16816(c2, a0, a1, a2, a3, q0, q1);
        MMA16816(c3, a0, a1, a2, a3, q2, q3);
    }

    int r0 = m0 + mw + (lane >> 2);
    int colb = n0 + nw + 2 * (lane & 3);
    float* accs[4] = {c0, c1, c2, c3};
#pragma unroll
    for (int t = 0; t < 4; t++) {
        float* cc = accs[t];
        if (r0 < M)
            *(__half2*)&C[(size_t)r0 * 256 + colb + t * 8] =
                __floats2half2_rn(cc[0], cc[1]);
        if (r0 + 8 < M)
            *(__half2*)&C[(size_t)(r0 + 8) * 256 + colb + t * 8] =
                __floats2half2_rn(cc[2], cc[3]);
    }

    float ps = 0.f, pd = 0.f, q = 0.f, ps8 = 0.f, pd8 = 0.f, q8 = 0.f;
#pragma unroll
    for (int t = 0; t < 4; t++) {
        int col = nw + 2 * (lane & 3) + t * 8;
        float a0 = s_sa[col], a1 = s_sa[col + 1];
        float d0 = s_da[col], d1 = s_da[col + 1];
        float* cc = accs[t];
        ps  += cc[0] * a0 + cc[1] * a1;
        pd  += cc[0] * d0 + cc[1] * d1;
        q   += cc[0] * cc[0] + cc[1] * cc[1];
        ps8 += cc[2] * a0 + cc[3] * a1;
        pd8 += cc[2] * d0 + cc[3] * d1;
        q8  += cc[2] * cc[2] + cc[3] * cc[3];
    }
#pragma unroll
    for (int o = 1; o < 4; o <<= 1) {
        ps  += __shfl_xor_sync(0xffffffffu, ps, o);
        pd  += __shfl_xor_sync(0xffffffffu, pd, o);
        q   += __shfl_xor_sync(0xffffffffu, q, o);
        ps8 += __shfl_xor_sync(0xffffffffu, ps8, o);
        pd8 += __shfl_xor_sync(0xffffffffu, pd8, o);
        q8  += __shfl_xor_sync(0xffffffffu, q8, o);
    }
    if ((lane & 3) == 0) {
        int r = mw + (lane >> 2);
        atomicAdd(&s_ps[r], ps);  atomicAdd(&s_pd[r], pd);  atomicAdd(&s_q[r], q);
        atomicAdd(&s_ps[r + 8], ps8); atomicAdd(&s_pd[r + 8], pd8); atomicAdd(&s_q[r + 8], q8);
    }
    __syncthreads();
    if (tid < 64 && m0 + tid < M) {
        int head = blockIdx.y;
        as_o[(m0 + tid) * 4 + head] = s_ps[tid] * LOG2E;
        ad_o[(m0 + tid) * 4 + head] = s_pd[tid] * LOG2E;
        if (ssq) atomicAdd(&ssq[m0 + tid], s_q[tid]);
    }
}

// ---- node trust + normalized struct feat + feature-norm finalize ------------
__global__ void k_trust(const float* __restrict__ sf, const float* __restrict__ Wt,
                        const float* __restrict__ bt) {
    int gt = blockIdx.x * blockDim.x + threadIdx.x;
    int w = gt >> 5;
    int lane = threadIdx.x & 31;
    if (w >= NN) return;
    float v = sf[w * 32 + lane];
    float d = v * Wt[lane];
    float q = v * v;
#pragma unroll
    for (int o = 1; o < 32; o <<= 1) {
        d += __shfl_xor_sync(0xffffffffu, d, o);
        q += __shfl_xor_sync(0xffffffffu, q, o);
    }
    float sii = 1.0f / fmaxf(sqrtf(q), 1e-8f);
    g_nsf[w * 32 + lane] = __float2half(v * sii);
    if (lane == 0) {
        float2 ni;
        float trust = 1.0f / (1.0f + __expf(-(d + bt[0])));
        ni.x = sqrtf(trust);
        ni.y = 1.0f / fmaxf(sqrtf(g_xfsq[w]), 1e-8f);
        g_ninfo[w] = ni;
    }
}

// -------- layer-1: 4-edge batched GAT aggregation, warp per dst node ---------
__global__ void k_l1(const float* __restrict__ bias1) {
    int gt = blockIdx.x * blockDim.x + threadIdx.x;
    int w = gt >> 5;
    int lane = threadIdx.x & 31;
    if (w >= NN) return;
    int head = lane >> 3;

    float adv = g_ad1[w * 4 + head];
    float p0 = ex2(lrelu(g_as1[w * 4 + head] + adv));
    float s = p0;
    float4 f0, f1;
    cvt8(*(const uint4*)&g_h[w * 256 + lane * 8], f0, f1);
    float4 acc0, acc1;
    acc0.x = p0 * f0.x; acc0.y = p0 * f0.y; acc0.z = p0 * f0.z; acc0.w = p0 * f0.w;
    acc1.x = p0 * f1.x; acc1.y = p0 * f1.y; acc1.z = p0 * f1.z; acc1.w = p0 * f1.w;

    int end = min(g_cnt[w], BCAP);
    const int* __restrict__ bp = &g_srcs[w * BCAP];

#define L1EDGE(JJ, AA, UU)                                                    \
    {                                                                         \
        float p = ex2(lrelu((AA) + adv));                                     \
        float4 b0, b1;                                                        \
        cvt8((UU), b0, b1);                                                   \
        s += p;                                                               \
        acc0.x = fmaf(p, b0.x, acc0.x);                                       \
        acc0.y = fmaf(p, b0.y, acc0.y);                                       \
        acc0.z = fmaf(p, b0.z, acc0.z);                                       \
        acc0.w = fmaf(p, b0.w, acc0.w);                                       \
        acc1.x = fmaf(p, b1.x, acc1.x);                                       \
        acc1.y = fmaf(p, b1.y, acc1.y);                                       \
        acc1.z = fmaf(p, b1.z, acc1.z);                                       \
        acc1.w = fmaf(p, b1.w, acc1.w);                                       \
    }

    int e = 0;
    for (; e + 4 <= end; e += 4) {
        int4 j4 = *(const int4*)&bp[e];           // bucket base 512B-aligned
        float a0s = __ldg(&g_as1[j4.x * 4 + head]);
        float a1s = __ldg(&g_as1[j4.y * 4 + head]);
        float a2s = __ldg(&g_as1[j4.z * 4 + head]);
        float a3s = __ldg(&g_as1[j4.w * 4 + head]);
        uint4 u0 = *(const uint4*)&g_h[(size_t)j4.x * 256 + lane * 8];
        uint4 u1 = *(const uint4*)&g_h[(size_t)j4.y * 256 + lane * 8];
        uint4 u2 = *(const uint4*)&g_h[(size_t)j4.z * 256 + lane * 8];
        uint4 u3 = *(const uint4*)&g_h[(size_t)j4.w * 256 + lane * 8];
        L1EDGE(j4.x, a0s, u0)
        L1EDGE(j4.y, a1s, u1)
        L1EDGE(j4.z, a2s, u2)
        L1EDGE(j4.w, a3s, u3)
    }
    for (; e < end; e++) {
        int j = __ldg(&bp[e]);
        float aj = __ldg(&g_as1[j * 4 + head]);
        uint4 u = *(const uint4*)&g_h[(size_t)j * 256 + lane * 8];
        L1EDGE(j, aj, u)
    }
#undef L1EDGE

    float r = frcp(s + 1e-16f);
    acc0.x *= r; acc0.y *= r; acc0.z *= r; acc0.w *= r;
    acc1.x *= r; acc1.y *= r; acc1.z *= r; acc1.w *= r;
#define HRED(v)                                     \
    v += __shfl_xor_sync(0xffffffffu, v, 8);        \
    v += __shfl_xor_sync(0xffffffffu, v, 16);
    HRED(acc0.x) HRED(acc0.y) HRED(acc0.z) HRED(acc0.w)
    HRED(acc1.x) HRED(acc1.y) HRED(acc1.z) HRED(acc1.w)
#undef HRED
    if (lane < 8) {
        const float4* bpb = (const float4*)&bias1[lane * 8];
        float4 b0 = bpb[0], b1 = bpb[1];
        float4 o0, o1;
        o0.x = fmaxf(0.25f * acc0.x + b0.x, 0.f);
        o0.y = fmaxf(0.25f * acc0.y + b0.y, 0.f);
        o0.z = fmaxf(0.25f * acc0.z + b0.z, 0.f);
        o0.w = fmaxf(0.25f * acc0.w + b0.w, 0.f);
        o1.x = fmaxf(0.25f * acc1.x + b1.x, 0.f);
        o1.y = fmaxf(0.25f * acc1.y + b1.y, 0.f);
        o1.z = fmaxf(0.25f * acc1.z + b1.z, 0.f);
        o1.w = fmaxf(0.25f * acc1.w + b1.w, 0.f);
        float4* op = (float4*)&g_h1[w * 64 + lane * 8];
        op[0] = o0;
        op[1] = o1;
    }
}

// -------- batchnorm statistics --------
__global__ void k_bnred() {
    int c = threadIdx.x & 63;
    int grp = threadIdx.x >> 6;
    int r0 = blockIdx.x * 4 + grp;
    int stride = gridDim.x * 4;
    float s = 0.f, q = 0.f;
    for (int r = r0; r < NN; r += stride) {
        float v = g_h1[r * 64 + c];
        s += v;
        q += v * v;
    }
    __shared__ float sh[256], shq[256];
    sh[threadIdx.x] = s;
    shq[threadIdx.x] = q;
    __syncthreads();
    if (threadIdx.x < 64) {
        for (int g = 1; g < 4; g++) {
            s += sh[threadIdx.x + 64 * g];
            q += shq[threadIdx.x + 64 * g];
        }
        atomicAdd(&g_bnsum[c], s);
        atomicAdd(&g_bnsq[c], q);
    }
}

__global__ void k_bnfin() {
    int c = threadIdx.x;
    if (c < 64) {
        float mu = g_bnsum[c] / (float)NN;
        float var = g_bnsq[c] / (float)NN - mu * mu;
        g_mu[c] = mu;
        g_istd[c] = rsqrtf(fmaxf(var, 0.f) + 1e-5f);
    }
}

// -------- layer-2: hybrid-gated GAT, pipelined (R7 form), warp per node ------
__global__ void k_l2(const float* __restrict__ We1, const float* __restrict__ be1,
                     const float* __restrict__ We2, const float* __restrict__ be2,
                     const float* __restrict__ betas, const float* __restrict__ bias2,
                     float* __restrict__ out) {
    __shared__ float sw[64];
    int tid = threadIdx.x;
    if (tid < 32) sw[tid] = We1[tid];
    else if (tid < 40) sw[tid] = be1[tid - 32];
    else if (tid < 48) sw[tid] = We2[tid - 40] * LOG2E;
    else if (tid == 48) sw[48] = be2[0] * LOG2E;
    else if (tid < 54) sw[tid] = betas[tid - 49] * LOG2E;
    __syncthreads();

    int gt = blockIdx.x * blockDim.x + tid;
    int w = gt >> 5;
    int lane = tid & 31;
    if (w >= NN) return;
    int head = lane >> 3;
    int hu_row = lane & 7;

    float4 xi0, xi1;
    cvt8(*(const uint4*)&g_x2[w * 256 + lane * 8], xi0, xi1);
    float nsfi = __half2float(g_nsf[w * 32 + lane]);
    float adv = g_ad2[w * 4 + head];
    float2 nw = g_ninfo[w];
    float tisq = nw.x, xii = nw.y;

    float s = 0.f;
    float4 acc0 = make_float4(0.f, 0.f, 0.f, 0.f);
    float4 acc1 = make_float4(0.f, 0.f, 0.f, 0.f);

    int end = min(g_cnt[w], BCAP);
    const int* __restrict__ bp = &g_srcs[w * BCAP];
    if (end > 0) {
        int j = __ldg(&bp[0]);
        uint4 u = *(const uint4*)&g_x2[(size_t)j * 256 + lane * 8];
        float nsfj = __half2float(__ldg(&g_nsf[j * 32 + lane]));
        float2 nj = __ldg(&g_ninfo[j]);
        float aj = __ldg(&g_as2[j * 4 + head]);
        for (int e = 0; e < end; e++) {
            int en = min(e + 1, end - 1);
            int j2 = __ldg(&bp[en]);
            uint4 u2 = *(const uint4*)&g_x2[(size_t)j2 * 256 + lane * 8];
            float nsfj2 = __half2float(__ldg(&g_nsf[j2 * 32 + lane]));
            float2 nj2 = __ldg(&g_ninfo[j2]);
            float aj2 = __ldg(&g_as2[j2 * 4 + head]);
            float4 b0, b1;
            cvt8(u, b0, b1);
            float fd = b0.x * xi0.x + b0.y * xi0.y + b0.z * xi0.z + b0.w * xi0.w +
                       b1.x * xi1.x + b1.y * xi1.y + b1.z * xi1.z + b1.w * xi1.w;
            float sd = nsfj * nsfi;
#pragma unroll
            for (int o = 1; o < 32; o <<= 1) {
                fd += __shfl_xor_sync(0xffffffffu, fd, o);
                sd += __shfl_xor_sync(0xffffffffu, sd, o);
            }
            float ssim = sd;
            float fsim = fd * xii * nj.y;
            float ag = ssim * fsim;
            float cf = fabsf(ssim - fsim);
            float hu = sw[hu_row * 4 + 0] * ssim + sw[hu_row * 4 + 1] * fsim +
                       sw[hu_row * 4 + 2] * ag + sw[hu_row * 4 + 3] * cf + sw[32 + hu_row];
            hu = fmaxf(hu, 0.f) * sw[40 + hu_row];
            hu += __shfl_xor_sync(0xffffffffu, hu, 1);
            hu += __shfl_xor_sync(0xffffffffu, hu, 2);
            hu += __shfl_xor_sync(0xffffffffu, hu, 4);
            float gate2 = hu + sw[48];
            float eb = frcp(1.0f + ex2(-gate2)) * fmaxf(ag, 0.f);
            float et = nj.x * tisq;
            float tb = et * fmaxf(0.5f * (ssim + fsim), 0.f);
            float gl = sw[49] * ssim + sw[50] * fsim + sw[51] * ag +
                       sw[52] * eb + sw[53] * tb;
            float p = ex2(lrelu(aj + adv) + gl);
            s += p;
            acc0.x = fmaf(p, b0.x, acc0.x);
            acc0.y = fmaf(p, b0.y, acc0.y);
            acc0.z = fmaf(p, b0.z, acc0.z);
            acc0.w = fmaf(p, b0.w, acc0.w);
            acc1.x = fmaf(p, b1.x, acc1.x);
            acc1.y = fmaf(p, b1.y, acc1.y);
            acc1.z = fmaf(p, b1.z, acc1.z);
            acc1.w = fmaf(p, b1.w, acc1.w);
            u = u2; nsfj = nsfj2; nj = nj2; aj = aj2;
        }
    }
    float r = frcp(s + 1e-16f);
    acc0.x *= r; acc0.y *= r; acc0.z *= r; acc0.w *= r;
    acc1.x *= r; acc1.y *= r; acc1.z *= r; acc1.w *= r;
#define HRED(v)                                     \
    v += __shfl_xor_sync(0xffffffffu, v, 8);        \
    v += __shfl_xor_sync(0xffffffffu, v, 16);
    HRED(acc0.x) HRED(acc0.y) HRED(acc0.z) HRED(acc0.w)
    HRED(acc1.x) HRED(acc1.y) HRED(acc1.z) HRED(acc1.w)
#undef HRED
    if (lane < 8) {
        const float4* bpb = (const float4*)&bias2[lane * 8];
        float4 b0 = bpb[0], b1 = bpb[1];
        float4 o0, o1;
        o0.x = 0.25f * acc0.x + b0.x;
        o0.y = 0.25f * acc0.y + b0.y;
        o0.z = 0.25f * acc0.z + b0.z;
        o0.w = 0.25f * acc0.w + b0.w;
        o1.x = 0.25f * acc1.x + b1.x;
        o1.y = 0.25f * acc1.y + b1.y;
        o1.z = 0.25f * acc1.z + b1.z;
        o1.w = 0.25f * acc1.w + b1.w;
        float4* op = (float4*)&out[w * 64 + lane * 8];
        op[0] = o0;
        op[1] = o1;
    }
}

// ---------------- host launch ----------------
extern "C" void kernel_launch(void* const* d_in, const int* in_sizes, int n_in,
                              void* d_out, int out_size) {
    const float* x    = (const float*)d_in[0];
    const int*   ei   = (const int*)d_in[1];
    const float* sf   = (const float*)d_in[2];
    const float* W1   = (const float*)d_in[3];
    const float* as1w = (const float*)d_in[4];
    const float* ad1w = (const float*)d_in[5];
    const float* b1   = (const float*)d_in[6];
    const float* W2   = (const float*)d_in[7];
    const float* as2w = (const float*)d_in[8];
    const float* ad2w = (const float*)d_in[9];
    const float* b2   = (const float*)d_in[10];
    const float* Wt   = (const float*)d_in[11];
    const float* bt   = (const float*)d_in[12];
    const float* We1  = (const float*)d_in[13];
    const float* be1  = (const float*)d_in[14];
    const float* We2  = (const float*)d_in[15];
    const float* be2  = (const float*)d_in[16];
    const float* betas = (const float*)d_in[17];
    float* out = (float*)d_out;

    __half *hP, *x2P;
    float *h1P, *muP, *istdP, *as1P, *ad1P, *as2P, *ad2P, *xfqP;
    cudaGetSymbolAddress((void**)&hP, g_h);
    cudaGetSymbolAddress((void**)&x2P, g_x2);
    cudaGetSymbolAddress((void**)&h1P, g_h1);
    cudaGetSymbolAddress((void**)&muP, g_mu);
    cudaGetSymbolAddress((void**)&istdP, g_istd);
    cudaGetSymbolAddress((void**)&as1P, g_as1);
    cudaGetSymbolAddress((void**)&ad1P, g_ad1);
    cudaGetSymbolAddress((void**)&as2P, g_as2);
    cudaGetSymbolAddress((void**)&ad2P, g_ad2);
    cudaGetSymbolAddress((void**)&xfqP, g_xfsq);

    const int TPB = 256;
    int nodeBlocks = (NN * 32 + TPB - 1) / TPB;

    k_init<<<(NN + TPB - 1) / TPB, TPB>>>();
    k_scatter<<<(EE / 4 + TPB - 1) / TPB, TPB>>>(ei);

    k_gemm_mma<<<dim3((NN + 63) / 64, 4), 256>>>(x, W1, hP, NN, 128,
                                                 nullptr, nullptr,
                                                 as1w, ad1w, as1P, ad1P, nullptr);
    k_l1<<<nodeBlocks, TPB>>>(b1);
    k_bnred<<<128, 256>>>();
    k_bnfin<<<1, 64>>>();

    k_gemm_mma<<<dim3((NN + 63) / 64, 4), 256>>>(h1P, W2, x2P, NN, 64,
                                                 muP, istdP,
                                                 as2w, ad2w, as2P, ad2P, xfqP);
    k_trust<<<nodeBlocks, TPB>>>(sf, Wt, bt);
    k_l2<<<nodeBlocks, TPB>>>(We1, be1, We2, be2, betas, b2, out);
}